// round 5
// baseline (speedup 1.0000x reference)
#include <cuda_runtime.h>
#include <cstdint>

// QORNN: B=256, T=1024, I=64, H=256, O=16
// Exact integer reformulation (bit-exact vs reference; rel_err 0.0 R2/R3):
//   x_q  = clip(rint(x*128), -128, 127)          int8, scale 1/128
//   W*_q = clip(rint(W*8), -8, 7)                int4-valued int8, scale 1/8
//   z    = (u + sum h_q*Wr_q) / 1024             int32 accum, exact in fp32 grid
//   m = relu(|z|+b); h_q = clip(rint(sign(z)*m*128), -128, 127)
// R4: u = xq@Wiq^T precomputed for all (b,t) by a parallel kernel into a
// __device__ int32 buffer (removes 16 dp4a + x logic from the sequential
// scan -> per-SMSP dp4a floor 640->512 cyc/step). Epilogue uses magic-number
// round-half-even:  rint((|z|/1024+b)*128) == rint(|z|*0.125f + 128*b) exactly.

#define TT 1024
#define NB 256
#define HH 256
#define NI 64
#define NO 16

__device__ uint32_t g_WiP[HH * 16];        // packed int8 x4 per hidden unit
__device__ uint32_t g_WrP[HH * 64];
__device__ uint32_t g_WoP[NO * 64];
__device__ int      g_U[(size_t)NB * TT * HH];   // 268 MB int32 scratch

__device__ __forceinline__ int clampi(int v, int lo, int hi) {
    return v < lo ? lo : (v > hi ? hi : v);
}

__device__ __forceinline__ uint32_t pack4(const float* p, float scale, int lo, int hi) {
    uint32_t w = 0;
#pragma unroll
    for (int j = 0; j < 4; j++) {
        int q = clampi((int)rintf(p[j] * scale), lo, hi);
        w |= ((uint32_t)(uint8_t)(int8_t)q) << (8 * j);
    }
    return w;
}

__global__ void prep_kernel(const float* __restrict__ Wi,
                            const float* __restrict__ Wr,
                            const float* __restrict__ Wo) {
    int c = threadIdx.x;  // 0..255
    for (int kw = 0; kw < 64; kw++)
        g_WrP[c * 64 + kw] = pack4(Wr + c * HH + kw * 4, 8.0f, -8, 7);
    for (int kw = 0; kw < 16; kw++)
        g_WiP[c * 16 + kw] = pack4(Wi + c * NI + kw * 4, 8.0f, -8, 7);
    if (c < NO) {
        for (int kw = 0; kw < 64; kw++)
            g_WoP[c * 64 + kw] = pack4(Wo + c * HH + kw * 4, 8.0f, -8, 7);
    }
}

// Input projection: u[r][t][unit] = sum_i xq[r][t][i] * Wiq[unit][i]  (int32)
// Grid: 256 rows x 8 t-chunks of 128. 256 threads = hidden unit.
#define UCHUNK 128
__global__ __launch_bounds__(256)
void u_kernel(const float* __restrict__ x) {
    __shared__ uint32_t sxq[UCHUNK * 16];     // 128 steps x 64 int8

    const int tid = threadIdx.x;
    const int r = blockIdx.x >> 3;
    const int t0 = (blockIdx.x & 7) * UCHUNK;

    // Quantize x[r][t0..t0+128][:] into smem (8192 elems, 32 per thread)
    const float* xr = x + ((size_t)r * TT + t0) * NI;
    int8_t* sb = (int8_t*)sxq;
#pragma unroll 4
    for (int k = 0; k < 32; k++) {
        int idx = tid + k * 256;
        float v = xr[idx];
        sb[idx] = (int8_t)clampi((int)rintf(v * 128.0f), -128, 127);
    }
    __syncthreads();

    uint32_t wi[16];
#pragma unroll
    for (int i = 0; i < 16; i++) wi[i] = g_WiP[tid * 16 + i];

    int* uout = g_U + ((size_t)r * TT + t0) * HH + tid;
#pragma unroll 2
    for (int t = 0; t < UCHUNK; t++) {
        const uint4* xw = (const uint4*)(sxq + t * 16);
        int a0 = 0, a1 = 0, a2 = 0, a3 = 0;
#pragma unroll
        for (int k = 0; k < 4; k++) {
            uint4 v = xw[k];
            a0 = __dp4a((int)v.x, (int)wi[4 * k + 0], a0);
            a1 = __dp4a((int)v.y, (int)wi[4 * k + 1], a1);
            a2 = __dp4a((int)v.z, (int)wi[4 * k + 2], a2);
            a3 = __dp4a((int)v.w, (int)wi[4 * k + 3], a3);
        }
        uout[t * HH] = (a0 + a1) + (a2 + a3);
    }
}

// Scan: one CTA = one batch row, 256 threads = hidden units, 2 CTAs/SM.
__global__ __launch_bounds__(256, 2)
void qornn_kernel(const float* __restrict__ b,
                  float* __restrict__ out) {
    __shared__ uint32_t sh_h[2][64];   // ping-pong h, 256 int8 each

    const int tid = threadIdx.x;
    const int r = blockIdx.x;

    uint32_t wr[64];
#pragma unroll
    for (int kw = 0; kw < 64; kw++) wr[kw] = g_WrP[tid * 64 + kw];
    const float bc128 = b[tid] * 128.0f;     // exact

    if (tid < 128) ((uint32_t*)sh_h)[tid] = 0u;

    const int* urow = g_U + (size_t)r * TT * HH + tid;
    int u_cur = __ldcs(urow);                 // u(t=0)
    __syncthreads();

    for (int t = 0; t < TT; t++) {
        const int cur = t & 1;
        const int nxt = cur ^ 1;

        // Prefetch u(t+1); DRAM latency hidden under the dp4a block
        int u_nxt = 0;
        if (t + 1 < TT) u_nxt = __ldcs(urow + (size_t)(t + 1) * HH);

        int s0 = 0, s1 = 0, s2 = 0, s3 = 0;
        const uint4* hw = (const uint4*)sh_h[cur];
#pragma unroll
        for (int k = 0; k < 16; k++) {
            uint4 v = hw[k];
            s0 = __dp4a((int)v.x, (int)wr[4 * k + 0], s0);
            s1 = __dp4a((int)v.y, (int)wr[4 * k + 1], s1);
            s2 = __dp4a((int)v.z, (int)wr[4 * k + 2], s2);
            s3 = __dp4a((int)v.w, (int)wr[4 * k + 3], s3);
        }

        const int z = ((s0 + s1) + (s2 + s3)) + u_cur;
        u_cur = u_nxt;

        // modrelu + quantize, branchless, magic-number round-half-even.
        // f = |z|*0.125 + 128b (FFMA, single rounding == reference rounding
        // scaled by 128); m = relu(f); rint(m) via +2^23+2^22 mantissa trick.
        {
            float f = fmaf(fabsf((float)z), 0.125f, bc128);
            float m = fmaxf(f, 0.0f);                       // m in [0, ~2^18)
            float tmagic = m + 12582912.0f;                 // 2^23 + 2^22
            int ni = __float_as_int(tmagic) - 0x4B400000;   // = rint(m)
            int pos = min(ni, 127);
            int neg = -min(ni, 128);
            int h = (z > 0) ? pos : ((z < 0) ? neg : 0);
            ((int8_t*)sh_h[nxt])[tid] = (int8_t)h;
        }

        __syncthreads();
    }

    // Output head: h_last is in buffer 0 (last t=1023 wrote nxt=0)
    if (tid < NO) {
        const uint32_t* hrow = sh_h[0];
        int acc = 0;
#pragma unroll
        for (int kw = 0; kw < 64; kw++)
            acc = __dp4a((int)hrow[kw], (int)g_WoP[tid * 64 + kw], acc);
        out[r * NO + tid] = (float)acc * (1.0f / 1024.0f);
    }
}

extern "C" void kernel_launch(void* const* d_in, const int* in_sizes, int n_in,
                              void* d_out, int out_size) {
    const float* inputs = (const float*)d_in[0];  // [256,1024,64]
    const float* Wi     = (const float*)d_in[1];  // [256,64]
    const float* Wr     = (const float*)d_in[2];  // [256,256]
    const float* Wo     = (const float*)d_in[3];  // [16,256]
    const float* b      = (const float*)d_in[4];  // [256]
    float* out = (float*)d_out;                   // [256,16]

    prep_kernel<<<1, 256>>>(Wi, Wr, Wo);
    u_kernel<<<NB * 8, 256>>>(inputs);
    qornn_kernel<<<NB, 256>>>(b, out);
}

// round 6
// speedup vs baseline: 1.2500x; 1.2500x over previous
#include <cuda_runtime.h>
#include <cstdint>

// QORNN: B=256, T=1024, I=64, H=256, O=16
// Exact integer reformulation (bit-exact vs reference; rel_err 0.0 R2-R4):
//   x_q  = clip(rint(x*128), -128, 127)          int8, scale 1/128
//   W*_q = clip(rint(W*8), -8, 7)                int4-valued int8, scale 1/8
//   z    = (u + sum h_q*Wr_q) / 1024             int32 accum, exact in fp32 grid
//   m = relu(|z|+b); h_q = clip(rint(sign(z)*m*128), -128, 127)
// R5 fixes vs R4:
//   - prep packing parallelized across 84 CTAs (was 1 CTA / 103 us)
//   - scan u-prefetch deepened to 4 steps (register pipeline, unroll-4) so
//     DRAM latency (~700cyc) is covered by ~4 step times (~2000cyc).

#define TT 1024
#define NB 256
#define HH 256
#define NI 64
#define NO 16

#define NWR (HH * 64)            // 16384 packed words
#define NWI (HH * 16)            // 4096
#define NWO (NO * 64)            // 1024
#define NPACK (NWR + NWI + NWO)  // 21504 = 84 * 256

__device__ uint32_t g_WiP[NWI];
__device__ uint32_t g_WrP[NWR];
__device__ uint32_t g_WoP[NWO];
__device__ int      g_U[(size_t)NB * TT * HH];   // 268 MB int32 scratch

__device__ __forceinline__ int clampi(int v, int lo, int hi) {
    return v < lo ? lo : (v > hi ? hi : v);
}

__device__ __forceinline__ uint32_t pack4(const float* p) {
    uint32_t w = 0;
#pragma unroll
    for (int j = 0; j < 4; j++) {
        int q = clampi((int)rintf(p[j] * 8.0f), -8, 7);
        w |= ((uint32_t)(uint8_t)(int8_t)q) << (8 * j);
    }
    return w;
}

// One packed word per thread; 84 CTAs x 256 threads = 21504 words.
__global__ __launch_bounds__(256)
void prep_kernel(const float* __restrict__ Wi,
                 const float* __restrict__ Wr,
                 const float* __restrict__ Wo) {
    int i = blockIdx.x * 256 + threadIdx.x;
    if (i < NWR) {
        int row = i >> 6, kw = i & 63;
        g_WrP[i] = pack4(Wr + row * HH + kw * 4);
    } else if (i < NWR + NWI) {
        int j = i - NWR;
        int row = j >> 4, kw = j & 15;
        g_WiP[j] = pack4(Wi + row * NI + kw * 4);
    } else if (i < NPACK) {
        int j = i - NWR - NWI;
        int row = j >> 6, kw = j & 63;
        g_WoP[j] = pack4(Wo + row * HH + kw * 4);
    }
}

// Input projection: u[r][t][unit] = sum_i xq[r][t][i] * Wiq[unit][i]  (int32)
// Grid: 256 rows x 8 t-chunks of 128. 256 threads = hidden unit.
#define UCHUNK 128
__global__ __launch_bounds__(256)
void u_kernel(const float* __restrict__ x) {
    __shared__ uint32_t sxq[UCHUNK * 16];     // 128 steps x 64 int8

    const int tid = threadIdx.x;
    const int r = blockIdx.x >> 3;
    const int t0 = (blockIdx.x & 7) * UCHUNK;

    const float* xr = x + ((size_t)r * TT + t0) * NI;
    int8_t* sb = (int8_t*)sxq;
#pragma unroll 4
    for (int k = 0; k < 32; k++) {
        int idx = tid + k * 256;
        float v = xr[idx];
        sb[idx] = (int8_t)clampi((int)rintf(v * 128.0f), -128, 127);
    }
    __syncthreads();

    uint32_t wi[16];
#pragma unroll
    for (int i = 0; i < 16; i++) wi[i] = g_WiP[tid * 16 + i];

    int* uout = g_U + ((size_t)r * TT + t0) * HH + tid;
#pragma unroll 2
    for (int t = 0; t < UCHUNK; t++) {
        const uint4* xw = (const uint4*)(sxq + t * 16);
        int a0 = 0, a1 = 0, a2 = 0, a3 = 0;
#pragma unroll
        for (int k = 0; k < 4; k++) {
            uint4 v = xw[k];
            a0 = __dp4a((int)v.x, (int)wi[4 * k + 0], a0);
            a1 = __dp4a((int)v.y, (int)wi[4 * k + 1], a1);
            a2 = __dp4a((int)v.z, (int)wi[4 * k + 2], a2);
            a3 = __dp4a((int)v.w, (int)wi[4 * k + 3], a3);
        }
        uout[t * HH] = (a0 + a1) + (a2 + a3);
    }
}

// Scan: one CTA = one batch row, 256 threads = hidden units, 2 CTAs/SM.
// Depth-4 register prefetch pipeline for u (loaded 4 steps ahead).
__global__ __launch_bounds__(256, 2)
void qornn_kernel(const float* __restrict__ b,
                  float* __restrict__ out) {
    __shared__ uint32_t sh_h[2][64];   // ping-pong h, 256 int8 each

    const int tid = threadIdx.x;
    const int r = blockIdx.x;

    uint32_t wr[64];
#pragma unroll
    for (int kw = 0; kw < 64; kw++) wr[kw] = g_WrP[tid * 64 + kw];
    const float bc128 = b[tid] * 128.0f;     // exact

    if (tid < 128) ((uint32_t*)sh_h)[tid] = 0u;

    const int* urow = g_U + (size_t)r * TT * HH + tid;
    int u0 = __ldcs(urow + 0 * HH);
    int u1 = __ldcs(urow + 1 * HH);
    int u2 = __ldcs(urow + 2 * HH);
    int u3 = __ldcs(urow + 3 * HH);
    __syncthreads();

    // One scan sub-step: consume ucur, dp4a over sh_h[CUR], write sh_h[CUR^1].
#define SCAN_STEP(CUR, UCUR)                                                  \
    {                                                                         \
        int s0 = 0, s1 = 0, s2 = 0, s3 = 0;                                   \
        const uint4* hw = (const uint4*)sh_h[CUR];                            \
        _Pragma("unroll")                                                     \
        for (int k = 0; k < 16; k++) {                                        \
            uint4 v = hw[k];                                                  \
            s0 = __dp4a((int)v.x, (int)wr[4 * k + 0], s0);                    \
            s1 = __dp4a((int)v.y, (int)wr[4 * k + 1], s1);                    \
            s2 = __dp4a((int)v.z, (int)wr[4 * k + 2], s2);                    \
            s3 = __dp4a((int)v.w, (int)wr[4 * k + 3], s3);                    \
        }                                                                     \
        const int z = ((s0 + s1) + (s2 + s3)) + (UCUR);                       \
        float f = fmaf(fabsf((float)z), 0.125f, bc128);                       \
        float m = fmaxf(f, 0.0f);                                             \
        float tm = m + 12582912.0f;                /* 2^23 + 2^22 */          \
        int ni = __float_as_int(tm) - 0x4B400000;  /* rint(m), half-even */   \
        int pos = min(ni, 127);                                               \
        int neg = -min(ni, 128);                                              \
        int hq = (z > 0) ? pos : ((z < 0) ? neg : 0);                         \
        ((int8_t*)sh_h[CUR ^ 1])[tid] = (int8_t)hq;                           \
        __syncthreads();                                                      \
    }

    for (int t = 0; t < TT; t += 4) {
        // sub-step 0 (cur=0): consume u0, refill for t+4
        {
            int uc = u0;
            u0 = (t + 4 < TT) ? __ldcs(urow + (size_t)(t + 4) * HH) : 0;
            SCAN_STEP(0, uc)
        }
        // sub-step 1 (cur=1)
        {
            int uc = u1;
            u1 = (t + 5 < TT) ? __ldcs(urow + (size_t)(t + 5) * HH) : 0;
            SCAN_STEP(1, uc)
        }
        // sub-step 2 (cur=0)
        {
            int uc = u2;
            u2 = (t + 6 < TT) ? __ldcs(urow + (size_t)(t + 6) * HH) : 0;
            SCAN_STEP(0, uc)
        }
        // sub-step 3 (cur=1)
        {
            int uc = u3;
            u3 = (t + 7 < TT) ? __ldcs(urow + (size_t)(t + 7) * HH) : 0;
            SCAN_STEP(1, uc)
        }
    }
#undef SCAN_STEP

    // Output head: h_last is in buffer 0 (t=1023 wrote CUR^1 = 0)
    if (tid < NO) {
        const uint32_t* hrow = sh_h[0];
        int acc = 0;
#pragma unroll
        for (int kw = 0; kw < 64; kw++)
            acc = __dp4a((int)hrow[kw], (int)g_WoP[tid * 64 + kw], acc);
        out[r * NO + tid] = (float)acc * (1.0f / 1024.0f);
    }
}

extern "C" void kernel_launch(void* const* d_in, const int* in_sizes, int n_in,
                              void* d_out, int out_size) {
    const float* inputs = (const float*)d_in[0];  // [256,1024,64]
    const float* Wi     = (const float*)d_in[1];  // [256,64]
    const float* Wr     = (const float*)d_in[2];  // [256,256]
    const float* Wo     = (const float*)d_in[3];  // [16,256]
    const float* b      = (const float*)d_in[4];  // [256]
    float* out = (float*)d_out;                   // [256,16]

    prep_kernel<<<(NPACK + 255) / 256, 256>>>(Wi, Wr, Wo);
    u_kernel<<<NB * 8, 256>>>(inputs);
    qornn_kernel<<<NB, 256>>>(b, out);
}

// round 7
// speedup vs baseline: 1.8880x; 1.5104x over previous
#include <cuda_runtime.h>
#include <cstdint>

// QORNN: B=256, T=1024, I=64, H=256, O=16
// Exact integer reformulation (bit-exact vs reference; rel_err 0.0 R2-R5):
//   x_q  = clip(rint(x*128), -128, 127)          int8, scale 1/128
//   W*_q = clip(rint(W*8), -8, 7)                int4-valued int8, scale 1/8
//   z    = (u + sum h_q*Wr_q) / 1024             int32 accum, exact in fp32 grid
//   m = relu(|z|+b); h_q = clip(rint(sign(z)*m*128), -128, 127)
// R6 change: scan's u prefetch moved from a register pipeline (R5: pushed past
// the 128-reg cap -> spills/de-batched LDS) to a register-free cp.async ring in
// SMEM (8 steps, two 4-step groups in flight). Per-thread wait_group semantics,
// no extra barriers, no live prefetch registers across barriers.

#define TT 1024
#define NB 256
#define HH 256
#define NI 64
#define NO 16

#define NWR (HH * 64)            // 16384 packed words
#define NWI (HH * 16)            // 4096
#define NWO (NO * 64)            // 1024
#define NPACK (NWR + NWI + NWO)  // 21504 = 84 * 256

__device__ uint32_t g_WiP[NWI];
__device__ uint32_t g_WrP[NWR];
__device__ uint32_t g_WoP[NWO];
// +8*HH pad so tail prefetch (t up to TT+7) needs no bounds check
__device__ int      g_U[(size_t)NB * TT * HH + 8 * HH];

__device__ __forceinline__ int clampi(int v, int lo, int hi) {
    return v < lo ? lo : (v > hi ? hi : v);
}

__device__ __forceinline__ uint32_t pack4(const float* p) {
    uint32_t w = 0;
#pragma unroll
    for (int j = 0; j < 4; j++) {
        int q = clampi((int)rintf(p[j] * 8.0f), -8, 7);
        w |= ((uint32_t)(uint8_t)(int8_t)q) << (8 * j);
    }
    return w;
}

__device__ __forceinline__ void cp_async4(void* smem_dst, const void* gsrc) {
    uint32_t s = (uint32_t)__cvta_generic_to_shared(smem_dst);
    asm volatile("cp.async.ca.shared.global [%0], [%1], 4;\n" :: "r"(s), "l"(gsrc));
}
#define CP_COMMIT() asm volatile("cp.async.commit_group;\n" ::: "memory")
#define CP_WAIT1()  asm volatile("cp.async.wait_group 1;\n" ::: "memory")

// One packed word per thread; 84 CTAs x 256 threads = 21504 words.
__global__ __launch_bounds__(256)
void prep_kernel(const float* __restrict__ Wi,
                 const float* __restrict__ Wr,
                 const float* __restrict__ Wo) {
    int i = blockIdx.x * 256 + threadIdx.x;
    if (i < NWR) {
        int row = i >> 6, kw = i & 63;
        g_WrP[i] = pack4(Wr + row * HH + kw * 4);
    } else if (i < NWR + NWI) {
        int j = i - NWR;
        int row = j >> 4, kw = j & 15;
        g_WiP[j] = pack4(Wi + row * NI + kw * 4);
    } else if (i < NPACK) {
        int j = i - NWR - NWI;
        int row = j >> 6, kw = j & 63;
        g_WoP[j] = pack4(Wo + row * HH + kw * 4);
    }
}

// Input projection: u[r][t][unit] = sum_i xq[r][t][i] * Wiq[unit][i]  (int32)
// Grid: 256 rows x 8 t-chunks of 128. 256 threads = hidden unit.
#define UCHUNK 128
__global__ __launch_bounds__(256)
void u_kernel(const float* __restrict__ x) {
    __shared__ uint32_t sxq[UCHUNK * 16];     // 128 steps x 64 int8

    const int tid = threadIdx.x;
    const int r = blockIdx.x >> 3;
    const int t0 = (blockIdx.x & 7) * UCHUNK;

    const float* xr = x + ((size_t)r * TT + t0) * NI;
    int8_t* sb = (int8_t*)sxq;
#pragma unroll 4
    for (int k = 0; k < 32; k++) {
        int idx = tid + k * 256;
        float v = xr[idx];
        sb[idx] = (int8_t)clampi((int)rintf(v * 128.0f), -128, 127);
    }
    __syncthreads();

    uint32_t wi[16];
#pragma unroll
    for (int i = 0; i < 16; i++) wi[i] = g_WiP[tid * 16 + i];

    int* uout = g_U + ((size_t)r * TT + t0) * HH + tid;
#pragma unroll 2
    for (int t = 0; t < UCHUNK; t++) {
        const uint4* xw = (const uint4*)(sxq + t * 16);
        int a0 = 0, a1 = 0, a2 = 0, a3 = 0;
#pragma unroll
        for (int k = 0; k < 4; k++) {
            uint4 v = xw[k];
            a0 = __dp4a((int)v.x, (int)wi[4 * k + 0], a0);
            a1 = __dp4a((int)v.y, (int)wi[4 * k + 1], a1);
            a2 = __dp4a((int)v.z, (int)wi[4 * k + 2], a2);
            a3 = __dp4a((int)v.w, (int)wi[4 * k + 3], a3);
        }
        uout[t * HH] = (a0 + a1) + (a2 + a3);
    }
}

// Scan: one CTA = one batch row, 256 threads = hidden units, 2 CTAs/SM.
// u staged via cp.async into an 8-step SMEM ring (two 4-step groups in flight).
__global__ __launch_bounds__(256, 2)
void qornn_kernel(const float* __restrict__ b,
                  float* __restrict__ out) {
    __shared__ uint32_t sh_h[2][64];   // ping-pong h, 256 int8 each
    __shared__ int su[8][HH];          // u ring: 8 steps x 256 units (8 KB)

    const int tid = threadIdx.x;
    const int r = blockIdx.x;
    const int* urow = g_U + (size_t)r * TT * HH + tid;

    // Kick off u prefetch (DRAM) before weight loads (L2) to overlap latency.
#pragma unroll
    for (int i = 0; i < 8; i++) {
        cp_async4(&su[i][tid], urow + (size_t)i * HH);
        if ((i & 3) == 3) CP_COMMIT();
    }

    uint32_t wr[64];
#pragma unroll
    for (int kw = 0; kw < 64; kw++) wr[kw] = g_WrP[tid * 64 + kw];
    const float bc128 = b[tid] * 128.0f;     // exact

    if (tid < 128) ((uint32_t*)sh_h)[tid] = 0u;
    __syncthreads();

    // One scan step: consume u from su slot, dp4a over sh_h[CUR], write CUR^1.
#define SCAN_STEP(CUR, SLOT)                                                  \
    {                                                                         \
        const int uc = su[SLOT][tid];                                         \
        int s0 = 0, s1 = 0, s2 = 0, s3 = 0;                                   \
        const uint4* hw = (const uint4*)sh_h[CUR];                            \
        _Pragma("unroll")                                                     \
        for (int k = 0; k < 16; k++) {                                        \
            uint4 v = hw[k];                                                  \
            s0 = __dp4a((int)v.x, (int)wr[4 * k + 0], s0);                    \
            s1 = __dp4a((int)v.y, (int)wr[4 * k + 1], s1);                    \
            s2 = __dp4a((int)v.z, (int)wr[4 * k + 2], s2);                    \
            s3 = __dp4a((int)v.w, (int)wr[4 * k + 3], s3);                    \
        }                                                                     \
        const int z = ((s0 + s1) + (s2 + s3)) + uc;                           \
        float f = fmaf(fabsf((float)z), 0.125f, bc128);                       \
        float m = fmaxf(f, 0.0f);                                             \
        float tm = m + 12582912.0f;                /* 2^23 + 2^22 */          \
        int ni = __float_as_int(tm) - 0x4B400000;  /* rint(m), half-even */   \
        int pos = min(ni, 127);                                               \
        int neg = -min(ni, 128);                                              \
        int hq = (z > 0) ? pos : ((z < 0) ? neg : 0);                         \
        ((int8_t*)sh_h[CUR ^ 1])[tid] = (int8_t)hq;                           \
        __syncthreads();                                                      \
    }

    for (int c = 0; c < TT / 4; c++) {
        const int t0 = c * 4;
        const int base = t0 & 7;                 // 0 or 4
        CP_WAIT1();                              // steps t0..t0+3 resident
        SCAN_STEP(0, (base + 0))
        SCAN_STEP(1, (base + 1))
        SCAN_STEP(0, (base + 2))
        SCAN_STEP(1, (base + 3))
        // Refill just-freed slots with steps t0+8..t0+11 (pad covers tail).
#pragma unroll
        for (int i = 0; i < 4; i++)
            cp_async4(&su[base + i][tid], urow + (size_t)(t0 + 8 + i) * HH);
        CP_COMMIT();
    }
#undef SCAN_STEP

    // Output head: h_last is in buffer 0 (t=1023 wrote CUR^1 = 0)
    if (tid < NO) {
        const uint32_t* hrow = sh_h[0];
        int acc = 0;
#pragma unroll
        for (int kw = 0; kw < 64; kw++)
            acc = __dp4a((int)hrow[kw], (int)g_WoP[tid * 64 + kw], acc);
        out[r * NO + tid] = (float)acc * (1.0f / 1024.0f);
    }
}

extern "C" void kernel_launch(void* const* d_in, const int* in_sizes, int n_in,
                              void* d_out, int out_size) {
    const float* inputs = (const float*)d_in[0];  // [256,1024,64]
    const float* Wi     = (const float*)d_in[1];  // [256,64]
    const float* Wr     = (const float*)d_in[2];  // [256,256]
    const float* Wo     = (const float*)d_in[3];  // [16,256]
    const float* b      = (const float*)d_in[4];  // [256]
    float* out = (float*)d_out;                   // [256,16]

    prep_kernel<<<(NPACK + 255) / 256, 256>>>(Wi, Wr, Wo);
    u_kernel<<<NB * 8, 256>>>(inputs);
    qornn_kernel<<<NB, 256>>>(b, out);
}

// round 9
// speedup vs baseline: 2.2055x; 1.1682x over previous
#include <cuda_runtime.h>
#include <cstdint>

// QORNN: B=256, T=1024, I=64, H=256, O=16
// Exact integer reformulation (bit-exact vs reference; rel_err 0.0 R2-R6):
//   x_q  = clip(rint(x*128), -128, 127)          int8, scale 1/128
//   W*_q = clip(rint(W*8), -8, 7)                int4-valued int8, scale 1/8
//   z    = (xq@Wiq + hq@Wrq) / 1024              int32 accum, exact in fp32 grid
//   m = relu(|z|+b); h_q = clip(rint(sign(z)*m*128), -128, 127)
// R8 = R7 with the modrelu_q constant fixed: 2^23*0.125 = 2^20 -> subtract
// 1048576.0f (R7 wrongly subtracted 131072 = 2^17, saturating every h).
// Fused single scan kernel + fast prep + short epilogue + CTA anti-phasing.

#define TT 1024
#define NB 256
#define HH 256
#define NI 64
#define NO 16

#define NWR (HH * 64)            // 16384 packed words
#define NWI (HH * 16)            // 4096
#define NWO (NO * 64)            // 1024
#define NPACK (NWR + NWI + NWO)  // 21504 = 84 * 256

__device__ uint32_t g_WiP[NWI];
__device__ uint32_t g_WrP[NWR];
__device__ uint32_t g_WoP[NWO];

__device__ __forceinline__ int clampi(int v, int lo, int hi) {
    return v < lo ? lo : (v > hi ? hi : v);
}

__device__ __forceinline__ uint32_t pack4(const float* p) {
    uint32_t w = 0;
#pragma unroll
    for (int j = 0; j < 4; j++) {
        int q = clampi((int)rintf(p[j] * 8.0f), -8, 7);
        w |= ((uint32_t)(uint8_t)(int8_t)q) << (8 * j);
    }
    return w;
}

// One packed word per thread; 84 CTAs x 256 threads = 21504 words.
__global__ __launch_bounds__(256)
void prep_kernel(const float* __restrict__ Wi,
                 const float* __restrict__ Wr,
                 const float* __restrict__ Wo) {
    int i = blockIdx.x * 256 + threadIdx.x;
    if (i < NWR) {
        int row = i >> 6, kw = i & 63;
        g_WrP[i] = pack4(Wr + row * HH + kw * 4);
    } else if (i < NWR + NWI) {
        int j = i - NWR;
        int row = j >> 4, kw = j & 15;
        g_WiP[j] = pack4(Wi + row * NI + kw * 4);
    } else if (i < NPACK) {
        int j = i - NWR - NWI;
        int row = j >> 6, kw = j & 63;
        g_WoP[j] = pack4(Wo + row * HH + kw * 4);
    }
}

// int8 quantize, round-half-even via magic add. v*128 is a power-of-two scale
// (exact), so the FMA's single rounding == reference's mul-then-round.
__device__ __forceinline__ int quant8(float v) {
    float tm = fmaf(v, 128.0f, 12582912.0f);        // 2^23 + 2^22
    int q = __float_as_int(tm) - 0x4B400000;        // rint(v*128), half-even
    return max(-128, min(127, q));
}

// modrelu + activation quantization, no I2F / no predicate selects.
// g = RN(az/8 + 128b) = 128*RN(|z|/1024 + b) (power-of-2 scaling commutes);
// relu and *128 commute; magic round = rint half-even; sign/clamp exact.
__device__ __forceinline__ int modrelu_q(int z, float bc128) {
    int az = abs(z);                                 // az < 2^19
    float azf = __int_as_float(0x4B000000 + az);     // 2^23 + az, exact
    float t8  = azf * 0.125f;                        // 2^20 + az/8, exact
    float f   = t8 - 1048576.0f;                     // az/8, exact (2^20!)
    float g   = f + bc128;                           // single RN (== ref)
    float m   = fmaxf(g, 0.0f);
    float tm  = m + 12582912.0f;                     // round half-even
    int ni    = __float_as_int(tm) - 0x4B400000;     // ni >= 0
    int s     = z >> 31;                             // -1 if z<0 else 0
    int t2    = min(ni, 127 - s);                    // bound 127 / 128
    int r     = (t2 ^ s) - s;                        // conditional negate
    int nz    = (z | -z) >> 31;                      // -1 iff z != 0
    return r & nz;                                   // sign(0) = 0
}

// Scan: one CTA = one batch row, 256 threads = hidden units, 2 CTAs/SM.
// Inline input projection; h and xq ping-pong through SMEM.
__global__ __launch_bounds__(256, 2)
void qornn_kernel(const float* __restrict__ x,
                  const float* __restrict__ b,
                  float* __restrict__ out) {
    __shared__ uint32_t sh_h[2][64];   // ping-pong h, 256 int8 each
    __shared__ uint32_t sh_x[2][16];   // ping-pong xq, 64 int8 each

    const int tid = threadIdx.x;
    const int r = blockIdx.x;

    uint32_t wr[64];
#pragma unroll
    for (int kw = 0; kw < 64; kw++) wr[kw] = g_WrP[tid * 64 + kw];
    uint32_t wi[16];
#pragma unroll
    for (int i = 0; i < 16; i++) wi[i] = g_WiP[tid * 16 + i];
    const float bc128 = b[tid] * 128.0f;     // exact

    if (tid < 128) ((uint32_t*)sh_h)[tid] = 0u;

    const float* xrow = x + (size_t)r * (TT * NI);
    if (tid < NI) {
        ((int8_t*)sh_x[0])[tid] = (int8_t)quant8(xrow[tid]);
    }

    // Anti-phase: second co-resident CTA (bid+148 shares SM with bid) starts
    // ~half a step later so its dp4a block covers the peer's serial chain.
    if (blockIdx.x >= 148) {
        long long c0 = clock64();
        while (clock64() - c0 < 550) { }
    }
    __syncthreads();

    // One step: dp4a x-part (sh_x[CUR]) + h-part (sh_h[CUR]) -> write CUR^1.
    // Prefetches x(TN) at top, quantizes+stores it at bottom (1-step lead).
#define SCAN_STEP(CUR, TN)                                                    \
    {                                                                         \
        float xv = 0.0f;                                                      \
        if (tid < NI) xv = xrow[(size_t)(TN) * NI + tid];                     \
        int s0 = 0, s1 = 0, s2 = 0, s3 = 0;                                   \
        const uint4* xw = (const uint4*)sh_x[CUR];                            \
        _Pragma("unroll")                                                     \
        for (int k = 0; k < 4; k++) {                                         \
            uint4 v = xw[k];                                                  \
            s0 = __dp4a((int)v.x, (int)wi[4 * k + 0], s0);                    \
            s1 = __dp4a((int)v.y, (int)wi[4 * k + 1], s1);                    \
            s2 = __dp4a((int)v.z, (int)wi[4 * k + 2], s2);                    \
            s3 = __dp4a((int)v.w, (int)wi[4 * k + 3], s3);                    \
        }                                                                     \
        const uint4* hw = (const uint4*)sh_h[CUR];                            \
        _Pragma("unroll")                                                     \
        for (int k = 0; k < 16; k++) {                                        \
            uint4 v = hw[k];                                                  \
            s0 = __dp4a((int)v.x, (int)wr[4 * k + 0], s0);                    \
            s1 = __dp4a((int)v.y, (int)wr[4 * k + 1], s1);                    \
            s2 = __dp4a((int)v.z, (int)wr[4 * k + 2], s2);                    \
            s3 = __dp4a((int)v.w, (int)wr[4 * k + 3], s3);                    \
        }                                                                     \
        const int z = ((s0 + s1) + (s2 + s3));                                \
        ((int8_t*)sh_h[CUR ^ 1])[tid] = (int8_t)modrelu_q(z, bc128);          \
        if (tid < NI) ((int8_t*)sh_x[CUR ^ 1])[tid] = (int8_t)quant8(xv);     \
        __syncthreads();                                                      \
    }

    for (int t = 0; t < TT; t += 2) {
        SCAN_STEP(0, (t + 1))
        SCAN_STEP(1, (t + 2 < TT ? t + 2 : TT - 1))
    }
#undef SCAN_STEP

    // Output head: h_last is in buffer 0 (t=1023: cur=1 wrote nxt=0)
    if (tid < NO) {
        const uint32_t* hrow = sh_h[0];
        int acc = 0;
#pragma unroll
        for (int kw = 0; kw < 64; kw++)
            acc = __dp4a((int)hrow[kw], (int)g_WoP[tid * 64 + kw], acc);
        out[r * NO + tid] = (float)acc * (1.0f / 1024.0f);
    }
}

extern "C" void kernel_launch(void* const* d_in, const int* in_sizes, int n_in,
                              void* d_out, int out_size) {
    const float* inputs = (const float*)d_in[0];  // [256,1024,64]
    const float* Wi     = (const float*)d_in[1];  // [256,64]
    const float* Wr     = (const float*)d_in[2];  // [256,256]
    const float* Wo     = (const float*)d_in[3];  // [16,256]
    const float* b      = (const float*)d_in[4];  // [256]
    float* out = (float*)d_out;                   // [256,16]

    prep_kernel<<<(NPACK + 255) / 256, 256>>>(Wi, Wr, Wo);
    qornn_kernel<<<NB, 256>>>(inputs, b, out);
}